// round 4
// baseline (speedup 1.0000x reference)
#include <cuda_runtime.h>
#include <math.h>

// ---------------- problem constants ----------------
#define B_TOT  15
#define NW     64
#define NSEQ   144
#define CDIM   192
#define NH     6
#define LDIM   32
#define MROWS  (B_TOT*NW*NSEQ)   // 138240
#define QKV_N  (3*CDIM)          // 576
#define WHCNT  (NW*NH)           // 384
#define NN     (NSEQ*NSEQ)       // 20736
#define SPAD   148               // padded row length for transposed smem tiles

// ---------------- scratch (device globals; no runtime alloc allowed) ------
__device__ float g_q[B_TOT*NW*NH*NSEQ*LDIM];   // (b_, w, h, n, l)
__device__ float g_k[B_TOT*NW*NH*NSEQ*LDIM];
__device__ float g_v[B_TOT*NW*NH*NSEQ*LDIM];
__device__ float g_y[MROWS*CDIM];              // (b_, w, n, h*32+l)
__device__ float g_bias[(size_t)WHCNT*NN];     // (w*6+h, n, m)

// ---------------- bias gather: materialize earth-position bias -----------
__global__ __launch_bounds__(256) void bias_gather_kernel(const float* __restrict__ table) {
    int wh = blockIdx.x;                 // w*6 + h
    float* dst = g_bias + (size_t)wh * NN;
    for (int i = threadIdx.x; i < NN; i += 256) {
        int n = i / NSEQ, m = i - n * NSEQ;
        int z1 = n / 72, h1 = (n / 12) % 6, w1 = n % 12;
        int z2 = m / 72, h2 = (m / 12) % 6, w2 = m % 12;
        int epi = (z1 + 2 * z2) * 828 + (h1 + 6 * h2) * 23 + (w1 - w2 + 11);
        dst[i] = table[epi * WHCNT + wh];
    }
}

// ---------------- QKV GEMM: (138240 x 192) @ (576 x 192)^T + b -----------
// BM=BN=64, BK=16, 256 threads, 4x4 microtile. Epilogue scatters into
// q/k/v scratch with (b_, w, h, n, l) layout.
__global__ __launch_bounds__(256) void qkv_gemm_kernel(
        const float* __restrict__ A, const float* __restrict__ W,
        const float* __restrict__ bias) {
    __shared__ float As[16][68];
    __shared__ float Bs[16][68];
    int tid = threadIdx.x;
    int rowBase = blockIdx.x * 64;
    int colBase = blockIdx.y * 64;
    int ty = tid >> 4, tx = tid & 15;
    int lr = tid >> 2;               // 0..63
    int lk = (tid & 3) << 2;         // 0,4,8,12

    float acc[4][4];
#pragma unroll
    for (int i = 0; i < 4; i++)
#pragma unroll
        for (int j = 0; j < 4; j++) acc[i][j] = 0.f;

    for (int kb = 0; kb < CDIM; kb += 16) {
        float4 av = *(const float4*)(A + (size_t)(rowBase + lr) * CDIM + kb + lk);
        float4 bv = *(const float4*)(W + (size_t)(colBase + lr) * CDIM + kb + lk);
        As[lk + 0][lr] = av.x; As[lk + 1][lr] = av.y;
        As[lk + 2][lr] = av.z; As[lk + 3][lr] = av.w;
        Bs[lk + 0][lr] = bv.x; Bs[lk + 1][lr] = bv.y;
        Bs[lk + 2][lr] = bv.z; Bs[lk + 3][lr] = bv.w;
        __syncthreads();
#pragma unroll
        for (int k = 0; k < 16; k++) {
            float4 a = *(const float4*)&As[k][ty * 4];
            float4 b = *(const float4*)&Bs[k][tx * 4];
            acc[0][0] += a.x * b.x; acc[0][1] += a.x * b.y; acc[0][2] += a.x * b.z; acc[0][3] += a.x * b.w;
            acc[1][0] += a.y * b.x; acc[1][1] += a.y * b.y; acc[1][2] += a.y * b.z; acc[1][3] += a.y * b.w;
            acc[2][0] += a.z * b.x; acc[2][1] += a.z * b.y; acc[2][2] += a.z * b.z; acc[2][3] += a.z * b.w;
            acc[3][0] += a.w * b.x; acc[3][1] += a.w * b.y; acc[3][2] += a.w * b.z; acc[3][3] += a.w * b.w;
        }
        __syncthreads();
    }

    int col0 = colBase + tx * 4;          // within one t-block (192 | 64)
    int t  = col0 / CDIM;                 // 0=q,1=k,2=v (uniform per block)
    int h  = (col0 % CDIM) >> 5;
    int l0 = col0 & 31;
    float* dst = (t == 0) ? g_q : (t == 1) ? g_k : g_v;
    float4 bb = *(const float4*)(bias + col0);
#pragma unroll
    for (int i = 0; i < 4; i++) {
        int row = rowBase + ty * 4 + i;
        int b_ = row / (NW * NSEQ);
        int w  = (row / NSEQ) % NW;
        int n  = row % NSEQ;
        size_t idx = ((((size_t)b_ * NW + w) * NH + h) * NSEQ + n) * LDIM + l0;
        float4 o = make_float4(acc[i][0] + bb.x, acc[i][1] + bb.y,
                               acc[i][2] + bb.z, acc[i][3] + bb.w);
        *(float4*)(dst + idx) = o;
    }
}

// ---------------- fused attention per (b_, w, h) window ------------------
__global__ __launch_bounds__(256) void attn_kernel(const float* __restrict__ mask) {
    extern __shared__ float sm[];
    float (*Qt)[SPAD] = (float(*)[SPAD])sm;                        // [l][n]
    float (*Kt)[SPAD] = (float(*)[SPAD])(sm + 32 * SPAD);          // [l][m]
    float (*Vs)[LDIM] = (float(*)[LDIM])(sm + 64 * SPAD);          // [m][l]
    float (*St)[SPAD] = (float(*)[SPAD])(sm + 64 * SPAD + NSEQ * LDIM); // [m][n]
    float* rinv = sm + 64 * SPAD + NSEQ * LDIM + NSEQ * SPAD;      // [n]

    int tid = threadIdx.x;
    int wh = blockIdx.x / B_TOT;      // w*6+h  (b_ fastest => bias reuse in L2)
    int b_ = blockIdx.x % B_TOT;
    int w  = wh / NH;
    int h  = wh % NH;

    const float* qp = g_q + ((size_t)b_ * WHCNT + wh) * (NSEQ * LDIM);
    const float* kp = g_k + ((size_t)b_ * WHCNT + wh) * (NSEQ * LDIM);
    const float* vp = g_v + ((size_t)b_ * WHCNT + wh) * (NSEQ * LDIM);

    // ---- load Q,K (transposed) and V into smem ----
    for (int idx = tid; idx < NSEQ * 8; idx += 256) {
        int n = idx >> 3, l4 = (idx & 7) << 2;
        float4 qv = *(const float4*)(qp + n * LDIM + l4);
        Qt[l4 + 0][n] = qv.x; Qt[l4 + 1][n] = qv.y;
        Qt[l4 + 2][n] = qv.z; Qt[l4 + 3][n] = qv.w;
        float4 kv = *(const float4*)(kp + n * LDIM + l4);
        Kt[l4 + 0][n] = kv.x; Kt[l4 + 1][n] = kv.y;
        Kt[l4 + 2][n] = kv.z; Kt[l4 + 3][n] = kv.w;
        *(float4*)&Vs[n][l4] = *(const float4*)(vp + n * LDIM + l4);
    }
    __syncthreads();

    // ---- S = Q @ K^T : 16x16 threads, 9x9 microtile, single pass --------
    int ty = tid >> 4, tx = tid & 15;
    {
        float acc[9][9];
#pragma unroll
        for (int i = 0; i < 9; i++)
#pragma unroll
            for (int j = 0; j < 9; j++) acc[i][j] = 0.f;

#pragma unroll 4
        for (int l = 0; l < LDIM; l++) {
            float a[9], b[9];
#pragma unroll
            for (int i = 0; i < 9; i++) a[i] = Qt[l][ty * 9 + i];
#pragma unroll
            for (int j = 0; j < 9; j++) b[j] = Kt[l][tx * 9 + j];
#pragma unroll
            for (int i = 0; i < 9; i++)
#pragma unroll
                for (int j = 0; j < 9; j++) acc[i][j] += a[i] * b[j];
        }

        const float scale = 0.17677669529663687f;   // 32^-0.5
        const float* bp = g_bias + (size_t)wh * NN;
        const float* mp = mask + ((size_t)b_ * NW + w) * NN;
#pragma unroll
        for (int i = 0; i < 9; i++) {
            int n = ty * 9 + i;
#pragma unroll
            for (int j = 0; j < 9; j++) {
                int m = tx * 9 + j;
                St[m][n] = acc[i][j] * scale + bp[n * NSEQ + m] + mp[n * NSEQ + m];
            }
        }
    }
    __syncthreads();

    // ---- softmax: one column n per thread --------------------------------
    if (tid < NSEQ) {
        int n = tid;
        float mx = -1e30f;
#pragma unroll 8
        for (int m = 0; m < NSEQ; m++) mx = fmaxf(mx, St[m][n]);
        float s = 0.f;
#pragma unroll 8
        for (int m = 0; m < NSEQ; m++) {
            float e = __expf(St[m][n] - mx);
            St[m][n] = e;
            s += e;
        }
        rinv[n] = 1.0f / s;
    }
    __syncthreads();

    // ---- out = P @ V : lanes over l (x8), rows strided by 32 -------------
    {
        int tx8 = tid & 7, tyy = tid >> 3;   // tyy: 0..31
        int l0 = tx8 * 4;
        float po[5][4];
#pragma unroll
        for (int i = 0; i < 5; i++)
#pragma unroll
            for (int j = 0; j < 4; j++) po[i][j] = 0.f;

        bool tail = (tyy < 16);              // row tyy+128 valid only then
#pragma unroll 4
        for (int m = 0; m < NSEQ; m++) {
            float4 bv = *(const float4*)&Vs[m][l0];
#pragma unroll
            for (int i = 0; i < 5; i++) {
                if (i < 4 || tail) {
                    float p = St[m][tyy + 32 * i];
                    po[i][0] += p * bv.x; po[i][1] += p * bv.y;
                    po[i][2] += p * bv.z; po[i][3] += p * bv.w;
                }
            }
        }

        float* yp = g_y + (((size_t)b_ * NW + w) * NSEQ) * CDIM + h * LDIM + l0;
#pragma unroll
        for (int i = 0; i < 5; i++) {
            if (i < 4 || tail) {
                int n = tyy + 32 * i;
                float r = rinv[n];
                *(float4*)(yp + (size_t)n * CDIM) =
                    make_float4(po[i][0] * r, po[i][1] * r, po[i][2] * r, po[i][3] * r);
            }
        }
    }
}

// ---------------- output projection: (138240 x 192) @ (192 x 192)^T + b --
__global__ __launch_bounds__(256) void proj_gemm_kernel(
        const float* __restrict__ W, const float* __restrict__ bias,
        float* __restrict__ out) {
    __shared__ float As[16][68];
    __shared__ float Bs[16][68];
    int tid = threadIdx.x;
    int rowBase = blockIdx.x * 64;
    int colBase = blockIdx.y * 64;
    int ty = tid >> 4, tx = tid & 15;
    int lr = tid >> 2;
    int lk = (tid & 3) << 2;

    float acc[4][4];
#pragma unroll
    for (int i = 0; i < 4; i++)
#pragma unroll
        for (int j = 0; j < 4; j++) acc[i][j] = 0.f;

    for (int kb = 0; kb < CDIM; kb += 16) {
        float4 av = *(const float4*)(g_y + (size_t)(rowBase + lr) * CDIM + kb + lk);
        float4 bv = *(const float4*)(W + (size_t)(colBase + lr) * CDIM + kb + lk);
        As[lk + 0][lr] = av.x; As[lk + 1][lr] = av.y;
        As[lk + 2][lr] = av.z; As[lk + 3][lr] = av.w;
        Bs[lk + 0][lr] = bv.x; Bs[lk + 1][lr] = bv.y;
        Bs[lk + 2][lr] = bv.z; Bs[lk + 3][lr] = bv.w;
        __syncthreads();
#pragma unroll
        for (int k = 0; k < 16; k++) {
            float4 a = *(const float4*)&As[k][ty * 4];
            float4 b = *(const float4*)&Bs[k][tx * 4];
            acc[0][0] += a.x * b.x; acc[0][1] += a.x * b.y; acc[0][2] += a.x * b.z; acc[0][3] += a.x * b.w;
            acc[1][0] += a.y * b.x; acc[1][1] += a.y * b.y; acc[1][2] += a.y * b.z; acc[1][3] += a.y * b.w;
            acc[2][0] += a.z * b.x; acc[2][1] += a.z * b.y; acc[2][2] += a.z * b.z; acc[2][3] += a.z * b.w;
            acc[3][0] += a.w * b.x; acc[3][1] += a.w * b.y; acc[3][2] += a.w * b.z; acc[3][3] += a.w * b.w;
        }
        __syncthreads();
    }

    int col0 = colBase + tx * 4;
    float4 bb = *(const float4*)(bias + col0);
#pragma unroll
    for (int i = 0; i < 4; i++) {
        int row = rowBase + ty * 4 + i;
        float4 o = make_float4(acc[i][0] + bb.x, acc[i][1] + bb.y,
                               acc[i][2] + bb.z, acc[i][3] + bb.w);
        *(float4*)(out + (size_t)row * CDIM + col0) = o;
    }
}

// ---------------- launch ---------------------------------------------------
extern "C" void kernel_launch(void* const* d_in, const int* in_sizes, int n_in,
                              void* d_out, int out_size) {
    const float* x          = (const float*)d_in[0];
    const float* mask       = (const float*)d_in[1];
    const float* qkv_w      = (const float*)d_in[2];
    const float* qkv_b      = (const float*)d_in[3];
    const float* proj_w     = (const float*)d_in[4];
    const float* proj_b     = (const float*)d_in[5];
    const float* bias_table = (const float*)d_in[6];
    float* out = (float*)d_out;

    const int ATTN_SMEM = (64 * SPAD + NSEQ * LDIM + NSEQ * SPAD + NSEQ) * 4;
    cudaFuncSetAttribute(attn_kernel, cudaFuncAttributeMaxDynamicSharedMemorySize,
                         ATTN_SMEM);

    bias_gather_kernel<<<WHCNT, 256>>>(bias_table);
    qkv_gemm_kernel<<<dim3(MROWS / 64, QKV_N / 64), 256>>>(x, qkv_w, qkv_b);
    attn_kernel<<<B_TOT * WHCNT, 256, ATTN_SMEM>>>(mask);
    proj_gemm_kernel<<<dim3(MROWS / 64, CDIM / 64), 256>>>(proj_w, proj_b, out);
}

// round 5
// speedup vs baseline: 2.0916x; 2.0916x over previous
#include <cuda_runtime.h>
#include <math.h>
#include <stdint.h>

// ---------------- problem constants ----------------
#define B_TOT  15
#define NW     64
#define NSEQ   144
#define CDIM   192
#define NH     6
#define LDIM   32
#define MROWS  (B_TOT*NW*NSEQ)   // 138240
#define QKV_N  (3*CDIM)          // 576
#define WHCNT  (NW*NH)           // 384
#define NN     (NSEQ*NSEQ)       // 20736

// ---------------- scratch (device globals) ------
__device__ float g_q[B_TOT*NW*NH*NSEQ*LDIM];   // (b_, w, h, n, l)
__device__ float g_k[B_TOT*NW*NH*NSEQ*LDIM];
__device__ float g_v[B_TOT*NW*NH*NSEQ*LDIM];
__device__ float g_y[MROWS*CDIM];              // (b_, w, n, h*32+l)
__device__ float g_bias[(size_t)WHCNT*NN];     // (w*6+h, n, m)

// ---------------- tf32 helpers -----------------
__device__ __forceinline__ uint32_t f2tf(float f) {
    uint32_t u;
    asm("cvt.rna.tf32.f32 %0, %1;" : "=r"(u) : "f"(f));
    return u;
}
__device__ __forceinline__ void mma8(float* c, const uint32_t* a, const uint32_t* b) {
    asm volatile(
        "mma.sync.aligned.m16n8k8.row.col.f32.tf32.tf32.f32 "
        "{%0,%1,%2,%3},{%4,%5,%6,%7},{%8,%9},{%0,%1,%2,%3};"
        : "+f"(c[0]), "+f"(c[1]), "+f"(c[2]), "+f"(c[3])
        : "r"(a[0]), "r"(a[1]), "r"(a[2]), "r"(a[3]), "r"(b[0]), "r"(b[1]));
}

// ---------------- bias gather -----------------
__global__ __launch_bounds__(256) void bias_gather_kernel(const float* __restrict__ table) {
    int wh = blockIdx.x;
    float* dst = g_bias + (size_t)wh * NN;
    for (int i = threadIdx.x; i < NN; i += 256) {
        int n = i / NSEQ, m = i - n * NSEQ;
        int z1 = n / 72, h1 = (n / 12) % 6, w1 = n % 12;
        int z2 = m / 72, h2 = (m / 12) % 6, w2 = m % 12;
        int epi = (z1 + 2 * z2) * 828 + (h1 + 6 * h2) * 23 + (w1 - w2 + 11);
        dst[i] = table[epi * WHCNT + wh];
    }
}

// ================= tf32 GEMM common =================
// BM=256, BN=64, BK=32, 256 threads (8 warps, 4m x 2n), warp tile 64x32.
// smem: padded k-stride 36 -> conflict-free fragment LDS.
#define GBM 256
#define GBN 64
#define GBK 32
#define GSTR 36
#define GA_SZ (GBM*GSTR)   // 9216 words per buffer
#define GB_SZ (GBN*GSTR)   // 2304
#define GSMEM ((2*GA_SZ + 2*GB_SZ)*4)   // 92160 B

struct GemmAcc { float c[4][4][4]; };   // [mi][ni][frag]

__device__ __forceinline__ void gemm_core(
        const float* __restrict__ Aglob, const float* __restrict__ Wglob,
        int rowBase, int colBase, uint32_t* sh, GemmAcc& acc,
        int wm, int wn, int tq, int tr) {
    uint32_t* As = sh;
    uint32_t* Bs = sh + 2 * GA_SZ;
    int tid = threadIdx.x;
    int aRow = tid >> 3, aCol = (tid & 7) << 2;
    const float* Ag = Aglob + (size_t)(rowBase + aRow) * CDIM + aCol;
    const float* Wg = Wglob + (size_t)(colBase + aRow) * CDIM + aCol;

#pragma unroll
    for (int mi = 0; mi < 4; mi++)
#pragma unroll
        for (int ni = 0; ni < 4; ni++)
#pragma unroll
            for (int f = 0; f < 4; f++) acc.c[mi][ni][f] = 0.f;

    float4 fa[8], fb[2];
#pragma unroll
    for (int i = 0; i < 8; i++) fa[i] = *(const float4*)(Ag + i * 32 * CDIM);
    fb[0] = *(const float4*)(Wg);
    fb[1] = *(const float4*)(Wg + 32 * CDIM);

    // store buffer 0
    {
        uint32_t* Ab = As;
        uint32_t* Bb = Bs;
#pragma unroll
        for (int i = 0; i < 8; i++) {
            uint32_t* p = Ab + (aRow + i * 32) * GSTR + aCol;
            p[0] = f2tf(fa[i].x); p[1] = f2tf(fa[i].y);
            p[2] = f2tf(fa[i].z); p[3] = f2tf(fa[i].w);
        }
        {
            uint32_t* p = Bb + aRow * GSTR + aCol;
            p[0] = f2tf(fb[0].x); p[1] = f2tf(fb[0].y);
            p[2] = f2tf(fb[0].z); p[3] = f2tf(fb[0].w);
            p = Bb + (aRow + 32) * GSTR + aCol;
            p[0] = f2tf(fb[1].x); p[1] = f2tf(fb[1].y);
            p[2] = f2tf(fb[1].z); p[3] = f2tf(fb[1].w);
        }
    }
    __syncthreads();

    for (int kb = 0; kb < CDIM; kb += GBK) {
        int buf = (kb / GBK) & 1;
        bool more = (kb + GBK) < CDIM;
        if (more) {
#pragma unroll
            for (int i = 0; i < 8; i++)
                fa[i] = *(const float4*)(Ag + kb + GBK + i * 32 * CDIM);
            fb[0] = *(const float4*)(Wg + kb + GBK);
            fb[1] = *(const float4*)(Wg + kb + GBK + 32 * CDIM);
        }
        // compute from buf
        {
            const uint32_t* Ab = As + buf * GA_SZ;
            const uint32_t* Bb = Bs + buf * GB_SZ;
#pragma unroll
            for (int ks = 0; ks < 4; ks++) {
                int k0 = ks * 8;
                uint32_t a[4][4], b[4][2];
#pragma unroll
                for (int mi = 0; mi < 4; mi++) {
                    const uint32_t* p = Ab + (wm * 64 + mi * 16 + tr) * GSTR + k0 + tq;
                    a[mi][0] = p[0];
                    a[mi][1] = p[8 * GSTR];
                    a[mi][2] = p[4];
                    a[mi][3] = p[8 * GSTR + 4];
                }
#pragma unroll
                for (int ni = 0; ni < 4; ni++) {
                    const uint32_t* p = Bb + (wn * 32 + ni * 8 + tr) * GSTR + k0 + tq;
                    b[ni][0] = p[0];
                    b[ni][1] = p[4];
                }
#pragma unroll
                for (int mi = 0; mi < 4; mi++)
#pragma unroll
                    for (int ni = 0; ni < 4; ni++)
                        mma8(acc.c[mi][ni], a[mi], b[ni]);
            }
        }
        if (more) {
            int nb = buf ^ 1;
            uint32_t* Ab = As + nb * GA_SZ;
            uint32_t* Bb = Bs + nb * GB_SZ;
#pragma unroll
            for (int i = 0; i < 8; i++) {
                uint32_t* p = Ab + (aRow + i * 32) * GSTR + aCol;
                p[0] = f2tf(fa[i].x); p[1] = f2tf(fa[i].y);
                p[2] = f2tf(fa[i].z); p[3] = f2tf(fa[i].w);
            }
            uint32_t* p = Bb + aRow * GSTR + aCol;
            p[0] = f2tf(fb[0].x); p[1] = f2tf(fb[0].y);
            p[2] = f2tf(fb[0].z); p[3] = f2tf(fb[0].w);
            p = Bb + (aRow + 32) * GSTR + aCol;
            p[0] = f2tf(fb[1].x); p[1] = f2tf(fb[1].y);
            p[2] = f2tf(fb[1].z); p[3] = f2tf(fb[1].w);
        }
        __syncthreads();
    }
}

// ---------------- QKV GEMM ----------------
__global__ __launch_bounds__(256) void qkv_gemm_tc(
        const float* __restrict__ A, const float* __restrict__ W,
        const float* __restrict__ bias) {
    extern __shared__ uint32_t sh[];
    int tid = threadIdx.x;
    int rowBase = blockIdx.x * GBM;
    int colBase = blockIdx.y * GBN;
    int wid = tid >> 5, t = tid & 31;
    int wm = wid >> 1, wn = wid & 1;
    int tq = t & 3, tr = t >> 2;

    GemmAcc acc;
    gemm_core(A, W, rowBase, colBase, sh, acc, wm, wn, tq, tr);

    int tsel = colBase / CDIM;                    // 0=q,1=k,2=v (uniform per block)
    float* dst = (tsel == 0) ? g_q : (tsel == 1) ? g_k : g_v;
#pragma unroll
    for (int mi = 0; mi < 4; mi++) {
        int rbase = rowBase + wm * 64 + mi * 16 + tr;
#pragma unroll
        for (int half = 0; half < 2; half++) {
            int r = rbase + half * 8;
            int b2 = r / (NW * NSEQ);
            int rem = r - b2 * (NW * NSEQ);
            int w2 = rem / NSEQ;
            int n = rem - w2 * NSEQ;
            size_t rowb = ((size_t)b2 * NW + w2) * NH;
#pragma unroll
            for (int ni = 0; ni < 4; ni++) {
                int c = colBase + wn * 32 + ni * 8 + 2 * tq;
                int cl = c - tsel * CDIM;
                int hh = cl >> 5, l0 = cl & 31;
                float2 bb = *(const float2*)(bias + c);
                size_t idx = ((rowb + hh) * NSEQ + n) * LDIM + l0;
                float2 o = make_float2(acc.c[mi][ni][half * 2] + bb.x,
                                       acc.c[mi][ni][half * 2 + 1] + bb.y);
                *(float2*)(dst + idx) = o;
            }
        }
    }
}

// ---------------- proj GEMM ----------------
__global__ __launch_bounds__(256) void proj_gemm_tc(
        const float* __restrict__ W, const float* __restrict__ bias,
        float* __restrict__ out) {
    extern __shared__ uint32_t sh[];
    int tid = threadIdx.x;
    int rowBase = blockIdx.x * GBM;
    int colBase = blockIdx.y * GBN;
    int wid = tid >> 5, t = tid & 31;
    int wm = wid >> 1, wn = wid & 1;
    int tq = t & 3, tr = t >> 2;

    GemmAcc acc;
    gemm_core(g_y, W, rowBase, colBase, sh, acc, wm, wn, tq, tr);

#pragma unroll
    for (int mi = 0; mi < 4; mi++) {
        int rbase = rowBase + wm * 64 + mi * 16 + tr;
#pragma unroll
        for (int half = 0; half < 2; half++) {
            int r = rbase + half * 8;
#pragma unroll
            for (int ni = 0; ni < 4; ni++) {
                int c = colBase + wn * 32 + ni * 8 + 2 * tq;
                float2 bb = *(const float2*)(bias + c);
                float2 o = make_float2(acc.c[mi][ni][half * 2] + bb.x,
                                       acc.c[mi][ni][half * 2 + 1] + bb.y);
                *(float2*)(out + (size_t)r * CDIM + c) = o;
            }
        }
    }
}

// ================= attention (tf32 mma) =================
// 576 threads = 18 warps per (b_, w, h) window.
#define ASTR 36     // padded stride for Q/K/V tiles (conflict-free frag LDS)
#define SSTR 148    // padded stride for S/P
#define AQ_SZ (NSEQ*ASTR)                 // 5184 words each
#define AS_SZ (NSEQ*SSTR)                 // 21312
#define ASMEM ((3*AQ_SZ + AS_SZ + NSEQ)*4)   // 148032 B

__global__ __launch_bounds__(576) void attn_tc(const float* __restrict__ mask) {
    extern __shared__ uint32_t ash[];
    uint32_t* Qs = ash;
    uint32_t* Ks = Qs + AQ_SZ;
    uint32_t* Vs = Ks + AQ_SZ;
    float* Ss = (float*)(Vs + AQ_SZ);     // [144][148]
    float* rinv = Ss + AS_SZ;             // [144]
    float* P2 = (float*)Qs;               // PV partial, reuses Q tile [144][36]

    int tid = threadIdx.x;
    int wh = blockIdx.x / B_TOT;          // b_ fastest -> bias L2 reuse
    int b_ = blockIdx.x - wh * B_TOT;
    int w_ = wh / NH;
    int h  = wh - w_ * NH;

    const float* qp = g_q + ((size_t)b_ * WHCNT + wh) * (NSEQ * LDIM);
    const float* kp = g_k + ((size_t)b_ * WHCNT + wh) * (NSEQ * LDIM);
    const float* vp = g_v + ((size_t)b_ * WHCNT + wh) * (NSEQ * LDIM);

    // ---- load Q,K,V -> smem as tf32, row-major [n][l], stride 36 ----
#pragma unroll
    for (int i = 0; i < 2; i++) {
        int v = tid + i * 576;            // 0..1151 float4s
        int n = v >> 3, c4 = (v & 7) << 2;
        float4 q = *(const float4*)(qp + n * LDIM + c4);
        float4 k = *(const float4*)(kp + n * LDIM + c4);
        float4 vv = *(const float4*)(vp + n * LDIM + c4);
        uint4 qu = make_uint4(f2tf(q.x), f2tf(q.y), f2tf(q.z), f2tf(q.w));
        uint4 ku = make_uint4(f2tf(k.x), f2tf(k.y), f2tf(k.z), f2tf(k.w));
        uint4 vu = make_uint4(f2tf(vv.x), f2tf(vv.y), f2tf(vv.z), f2tf(vv.w));
        *(uint4*)(Qs + n * ASTR + c4) = qu;
        *(uint4*)(Ks + n * ASTR + c4) = ku;
        *(uint4*)(Vs + n * ASTR + c4) = vu;
    }
    __syncthreads();

    int wid = tid >> 5, t = tid & 31;
    int tq = t & 3, tr = t >> 2;

    // ---- mma1: S = Q @ K^T, warp grid 9(m) x 2(n-half of 72) ----
    {
        int wm = wid >> 1, nh = wid & 1;
        float c[9][4];
#pragma unroll
        for (int ni = 0; ni < 9; ni++)
#pragma unroll
            for (int f = 0; f < 4; f++) c[ni][f] = 0.f;

#pragma unroll
        for (int ks = 0; ks < 4; ks++) {
            int k0 = ks * 8;
            uint32_t a[4];
            const uint32_t* ap = Qs + (wm * 16 + tr) * ASTR + k0 + tq;
            a[0] = ap[0]; a[1] = ap[8 * ASTR]; a[2] = ap[4]; a[3] = ap[8 * ASTR + 4];
            uint32_t b[9][2];
#pragma unroll
            for (int ni = 0; ni < 9; ni++) {
                const uint32_t* bp2 = Ks + (nh * 72 + ni * 8 + tr) * ASTR + k0 + tq;
                b[ni][0] = bp2[0];
                b[ni][1] = bp2[4];
            }
#pragma unroll
            for (int ni = 0; ni < 9; ni++) mma8(c[ni], a, b[ni]);
        }

        const float scale = 0.17677669529663687f;   // 32^-0.5
        const float* bp = g_bias + (size_t)wh * NN;
        const float* mp = mask + ((size_t)b_ * NW + w_) * NN;
        int n0 = wm * 16 + tr, n1 = n0 + 8;
#pragma unroll
        for (int ni = 0; ni < 9; ni++) {
            int m0 = nh * 72 + ni * 8 + 2 * tq;
            float2 bb0 = *(const float2*)(bp + n0 * NSEQ + m0);
            float2 bb1 = *(const float2*)(bp + n1 * NSEQ + m0);
            float2 mm0 = *(const float2*)(mp + n0 * NSEQ + m0);
            float2 mm1 = *(const float2*)(mp + n1 * NSEQ + m0);
            *(float2*)(Ss + n0 * SSTR + m0) =
                make_float2(c[ni][0] * scale + bb0.x + mm0.x,
                            c[ni][1] * scale + bb0.y + mm0.y);
            *(float2*)(Ss + n1 * SSTR + m0) =
                make_float2(c[ni][2] * scale + bb1.x + mm1.x,
                            c[ni][3] * scale + bb1.y + mm1.y);
        }
    }
    __syncthreads();

    // ---- softmax over rows: 4 threads per row, shfl reduce ----
    {
        int n = tid >> 2, seg = tid & 3;
        float* row = Ss + n * SSTR + seg * 36;
        float mx = -1e30f;
#pragma unroll
        for (int i = 0; i < 36; i++) mx = fmaxf(mx, row[i]);
        mx = fmaxf(mx, __shfl_xor_sync(0xffffffffu, mx, 1));
        mx = fmaxf(mx, __shfl_xor_sync(0xffffffffu, mx, 2));
        float s = 0.f;
#pragma unroll
        for (int i = 0; i < 36; i++) {
            float e = __expf(row[i] - mx);
            s += e;
            row[i] = __uint_as_float(f2tf(e));   // store P as tf32 bits
        }
        s += __shfl_xor_sync(0xffffffffu, s, 1);
        s += __shfl_xor_sync(0xffffffffu, s, 2);
        if (seg == 0) rinv[n] = 1.0f / s;
    }
    __syncthreads();

    // ---- PV: out = P @ V, split-K (2 halves of 72), warp tile 16x32 ----
    {
        int wm = wid % 9, kh = wid / 9;
        float c2[4][4];
#pragma unroll
        for (int ni = 0; ni < 4; ni++)
#pragma unroll
            for (int f = 0; f < 4; f++) c2[ni][f] = 0.f;

#pragma unroll
        for (int ks = 0; ks < 9; ks++) {
            int k0 = kh * 72 + ks * 8;
            uint32_t a[4];
            const uint32_t* ap = (const uint32_t*)Ss + (wm * 16 + tr) * SSTR + k0 + tq;
            a[0] = ap[0]; a[1] = ap[8 * SSTR]; a[2] = ap[4]; a[3] = ap[8 * SSTR + 4];
            uint32_t b[4][2];
#pragma unroll
            for (int ni = 0; ni < 4; ni++) {
                const uint32_t* bp2 = Vs + (k0 + tq) * ASTR + ni * 8 + tr;
                b[ni][0] = bp2[0];
                b[ni][1] = bp2[4 * ASTR];
            }
#pragma unroll
            for (int ni = 0; ni < 4; ni++) mma8(c2[ni], a, b[ni]);
        }

        if (kh == 1) {
            int n0 = wm * 16 + tr;
#pragma unroll
            for (int ni = 0; ni < 4; ni++) {
                int l0 = ni * 8 + 2 * tq;
                *(float2*)(P2 + n0 * ASTR + l0) = make_float2(c2[ni][0], c2[ni][1]);
                *(float2*)(P2 + (n0 + 8) * ASTR + l0) = make_float2(c2[ni][2], c2[ni][3]);
            }
        }
        __syncthreads();
        if (kh == 0) {
            float* yp = g_y + (((size_t)b_ * NW + w_) * NSEQ) * CDIM + h * LDIM;
            int n0 = wm * 16 + tr, n1 = n0 + 8;
            float r0 = rinv[n0], r1 = rinv[n1];
#pragma unroll
            for (int ni = 0; ni < 4; ni++) {
                int l0 = ni * 8 + 2 * tq;
                float2 p0 = *(float2*)(P2 + n0 * ASTR + l0);
                float2 p1 = *(float2*)(P2 + (n0 + 8) * ASTR + l0);
                *(float2*)(yp + (size_t)n0 * CDIM + l0) =
                    make_float2((c2[ni][0] + p0.x) * r0, (c2[ni][1] + p0.y) * r0);
                *(float2*)(yp + (size_t)n1 * CDIM + l0) =
                    make_float2((c2[ni][2] + p1.x) * r1, (c2[ni][3] + p1.y) * r1);
            }
        }
    }
}

// ---------------- launch ----------------
extern "C" void kernel_launch(void* const* d_in, const int* in_sizes, int n_in,
                              void* d_out, int out_size) {
    const float* x          = (const float*)d_in[0];
    const float* mask       = (const float*)d_in[1];
    const float* qkv_w      = (const float*)d_in[2];
    const float* qkv_b      = (const float*)d_in[3];
    const float* proj_w     = (const float*)d_in[4];
    const float* proj_b     = (const float*)d_in[5];
    const float* bias_table = (const float*)d_in[6];
    float* out = (float*)d_out;

    static bool attr_done = false;
    if (!attr_done) {
        cudaFuncSetAttribute(qkv_gemm_tc, cudaFuncAttributeMaxDynamicSharedMemorySize, GSMEM);
        cudaFuncSetAttribute(proj_gemm_tc, cudaFuncAttributeMaxDynamicSharedMemorySize, GSMEM);
        cudaFuncSetAttribute(attn_tc, cudaFuncAttributeMaxDynamicSharedMemorySize, ASMEM);
        attr_done = true;
    }

    bias_gather_kernel<<<WHCNT, 256>>>(bias_table);
    qkv_gemm_tc<<<dim3(MROWS / GBM, QKV_N / GBN), 256, GSMEM>>>(x, qkv_w, qkv_b);
    attn_tc<<<B_TOT * WHCNT, 576, ASMEM>>>(mask);
    proj_gemm_tc<<<dim3(MROWS / GBM, CDIM / GBN), 256, GSMEM>>>(proj_w, proj_b, out);
}

// round 9
// speedup vs baseline: 2.2142x; 1.0586x over previous
#include <cuda_runtime.h>
#include <math.h>
#include <stdint.h>

// ---------------- problem constants ----------------
#define B_TOT  15
#define NW     64
#define NSEQ   144
#define CDIM   192
#define NH     6
#define LDIM   32
#define MROWS  (B_TOT*NW*NSEQ)   // 138240
#define QKV_N  (3*CDIM)          // 576
#define WHCNT  (NW*NH)           // 384
#define NN     (NSEQ*NSEQ)       // 20736

// ---------------- scratch (device globals) ------
__device__ float g_q[B_TOT*NW*NH*NSEQ*LDIM];   // (b_, w, h, n, l)
__device__ float g_k[B_TOT*NW*NH*NSEQ*LDIM];
__device__ float g_v[B_TOT*NW*NH*NSEQ*LDIM];
__device__ float g_y[MROWS*CDIM];              // (b_, w, n, h*32+l)
__device__ float g_bias[(size_t)WHCNT*NN];     // (w*6+h, n, m)

// ---------------- mma / cp.async helpers -----------------
__device__ __forceinline__ void mma8(float* c, const uint32_t* a, const uint32_t* b) {
    asm volatile(
        "mma.sync.aligned.m16n8k8.row.col.f32.tf32.tf32.f32 "
        "{%0,%1,%2,%3},{%4,%5,%6,%7},{%8,%9},{%0,%1,%2,%3};"
        : "+f"(c[0]), "+f"(c[1]), "+f"(c[2]), "+f"(c[3])
        : "r"(a[0]), "r"(a[1]), "r"(a[2]), "r"(a[3]), "r"(b[0]), "r"(b[1]));
}
__device__ __forceinline__ void cp16(uint32_t dst, const void* src) {
    asm volatile("cp.async.cg.shared.global [%0], [%1], 16;\n" :: "r"(dst), "l"(src));
}
__device__ __forceinline__ void cp_commit() {
    asm volatile("cp.async.commit_group;\n" ::);
}
template<int N> __device__ __forceinline__ void cp_wait() {
    asm volatile("cp.async.wait_group %0;\n" :: "n"(N));
}

// ---------------- bias gather -----------------
__global__ __launch_bounds__(256) void bias_gather_kernel(const float* __restrict__ table) {
    int wh = blockIdx.x;
    float* dst = g_bias + (size_t)wh * NN;
    for (int i = threadIdx.x; i < NN; i += 256) {
        int n = i / NSEQ, m = i - n * NSEQ;
        int z1 = n / 72, h1 = (n / 12) % 6, w1 = n % 12;
        int z2 = m / 72, h2 = (m / 12) % 6, w2 = m % 12;
        int epi = (z1 + 2 * z2) * 828 + (h1 + 6 * h2) * 23 + (w1 - w2 + 11);
        dst[i] = table[epi * WHCNT + wh];
    }
}

// ================= tf32 GEMM (cp.async 3-stage) =================
// BM=128, BN=64, BK=32, 256 threads (8 warps 4m x 2n), warp tile 32x32.
#define GBM 128
#define GBN 64
#define GBK 32
#define GSTR 36
#define GA_ST (GBM*GSTR)                 // 4608 words / stage
#define GB_ST (GBN*GSTR)                 // 2304
#define NSTAGE 3
#define GSMEM (NSTAGE*(GA_ST+GB_ST)*4)   // 82944 B

struct GAcc { float c[2][4][4]; };       // [mi][ni][frag]

__device__ __forceinline__ void gemm_core(
        const float* __restrict__ Aglob, const float* __restrict__ Wglob,
        int rowBase, int colBase, float* sh, GAcc& acc,
        int wm, int wn, int tq, int tr) {
    int tid = threadIdx.x;
    int lrow = tid >> 3;                 // 0..31
    int lc4  = tid & 7;                  // float4 column 0..7
    const float* Ag = Aglob + (size_t)(rowBase + lrow) * CDIM + lc4 * 4;
    const float* Wg = Wglob + (size_t)(colBase + lrow) * CDIM + lc4 * 4;
    uint32_t sbase = (uint32_t)__cvta_generic_to_shared(sh);

#pragma unroll
    for (int mi = 0; mi < 2; mi++)
#pragma unroll
        for (int ni = 0; ni < 4; ni++)
#pragma unroll
            for (int f = 0; f < 4; f++) acc.c[mi][ni][f] = 0.f;

    // prologue: stages 0..NSTAGE-2
#pragma unroll
    for (int s = 0; s < NSTAGE - 1; s++) {
        uint32_t ab = sbase + (s * (GA_ST + GB_ST)) * 4;
        uint32_t bb = ab + GA_ST * 4;
#pragma unroll
        for (int i = 0; i < 4; i++)
            cp16(ab + ((lrow + i * 32) * GSTR + lc4 * 4) * 4, Ag + s * GBK + (size_t)i * 32 * CDIM);
#pragma unroll
        for (int i = 0; i < 2; i++)
            cp16(bb + ((lrow + i * 32) * GSTR + lc4 * 4) * 4, Wg + s * GBK + (size_t)i * 32 * CDIM);
        cp_commit();
    }

    const int NK = CDIM / GBK;           // 6
    for (int kt = 0; kt < NK; kt++) {
        cp_wait<NSTAGE - 2>();
        __syncthreads();
        int nkt = kt + NSTAGE - 1;
        if (nkt < NK) {
            int s = nkt % NSTAGE;
            uint32_t ab = sbase + (s * (GA_ST + GB_ST)) * 4;
            uint32_t bb = ab + GA_ST * 4;
#pragma unroll
            for (int i = 0; i < 4; i++)
                cp16(ab + ((lrow + i * 32) * GSTR + lc4 * 4) * 4, Ag + nkt * GBK + (size_t)i * 32 * CDIM);
#pragma unroll
            for (int i = 0; i < 2; i++)
                cp16(bb + ((lrow + i * 32) * GSTR + lc4 * 4) * 4, Wg + nkt * GBK + (size_t)i * 32 * CDIM);
        }
        cp_commit();

        const uint32_t* Ab = (const uint32_t*)sh + (kt % NSTAGE) * (GA_ST + GB_ST);
        const uint32_t* Bb = Ab + GA_ST;
#pragma unroll
        for (int ks = 0; ks < 4; ks++) {
            int k0 = ks * 8;
            uint32_t a[2][4];
#pragma unroll
            for (int mi = 0; mi < 2; mi++) {
                const uint32_t* p = Ab + (wm * 32 + mi * 16 + tr) * GSTR + k0 + tq;
                a[mi][0] = p[0]; a[mi][1] = p[8 * GSTR];
                a[mi][2] = p[4]; a[mi][3] = p[8 * GSTR + 4];
            }
#pragma unroll
            for (int ni = 0; ni < 4; ni++) {
                uint32_t b[2];
                const uint32_t* p = Bb + (wn * 32 + ni * 8 + tr) * GSTR + k0 + tq;
                b[0] = p[0]; b[1] = p[4];
#pragma unroll
                for (int mi = 0; mi < 2; mi++) mma8(acc.c[mi][ni], a[mi], b);
            }
        }
    }
}

// ---------------- QKV GEMM ----------------
__global__ __launch_bounds__(256, 2) void qkv_gemm_tc(
        const float* __restrict__ A, const float* __restrict__ W,
        const float* __restrict__ bias) {
    extern __shared__ float sh[];
    int tid = threadIdx.x;
    int rowBase = blockIdx.x * GBM;
    int colBase = blockIdx.y * GBN;
    int wid = tid >> 5, t = tid & 31;
    int wm = wid & 3, wn = wid >> 2;
    int tq = t & 3, tr = t >> 2;

    GAcc acc;
    gemm_core(A, W, rowBase, colBase, sh, acc, wm, wn, tq, tr);

    int tsel = colBase / CDIM;           // 0=q,1=k,2=v (uniform per block)
    float* dst = (tsel == 0) ? g_q : (tsel == 1) ? g_k : g_v;
#pragma unroll
    for (int mi = 0; mi < 2; mi++) {
#pragma unroll
        for (int half = 0; half < 2; half++) {
            int r = rowBase + wm * 32 + mi * 16 + half * 8 + tr;
            int b2 = r / (NW * NSEQ);
            int rem = r - b2 * (NW * NSEQ);
            int w2 = rem / NSEQ;
            int n = rem - w2 * NSEQ;
            size_t rowb = ((size_t)b2 * NW + w2) * NH;
#pragma unroll
            for (int ni = 0; ni < 4; ni++) {
                int c = colBase + wn * 32 + ni * 8 + 2 * tq;
                int cl = c - tsel * CDIM;
                int hh = cl >> 5, l0 = cl & 31;
                float2 bb = *(const float2*)(bias + c);
                size_t idx = ((rowb + hh) * NSEQ + n) * LDIM + l0;
                *(float2*)(dst + idx) =
                    make_float2(acc.c[mi][ni][half * 2] + bb.x,
                                acc.c[mi][ni][half * 2 + 1] + bb.y);
            }
        }
    }
}

// ---------------- proj GEMM ----------------
__global__ __launch_bounds__(256, 2) void proj_gemm_tc(
        const float* __restrict__ W, const float* __restrict__ bias,
        float* __restrict__ out) {
    extern __shared__ float sh[];
    int tid = threadIdx.x;
    int rowBase = blockIdx.x * GBM;
    int colBase = blockIdx.y * GBN;
    int wid = tid >> 5, t = tid & 31;
    int wm = wid & 3, wn = wid >> 2;
    int tq = t & 3, tr = t >> 2;

    GAcc acc;
    gemm_core(g_y, W, rowBase, colBase, sh, acc, wm, wn, tq, tr);

#pragma unroll
    for (int mi = 0; mi < 2; mi++) {
#pragma unroll
        for (int half = 0; half < 2; half++) {
            int r = rowBase + wm * 32 + mi * 16 + half * 8 + tr;
#pragma unroll
            for (int ni = 0; ni < 4; ni++) {
                int c = colBase + wn * 32 + ni * 8 + 2 * tq;
                float2 bb = *(const float2*)(bias + c);
                *(float2*)(out + (size_t)r * CDIM + c) =
                    make_float2(acc.c[mi][ni][half * 2] + bb.x,
                                acc.c[mi][ni][half * 2 + 1] + bb.y);
            }
        }
    }
}

// ================= attention: 2 CTAs per window (72 rows each) =================
// 320 threads = 10 warps, M padded 72->80 (5 m16-tiles).
#define ASTR 36
#define SSTR 146
#define HROWS 72
#define MPAD  80
#define AQ_OFF 0
#define AK_OFF (MPAD*ASTR)                     // 2880
#define AV_OFF (AK_OFF + NSEQ*ASTR)            // 8064
#define AS_OFF (AV_OFF + NSEQ*ASTR)            // 13248
#define AR_OFF (AS_OFF + MPAD*SSTR)            // 24928
#define ASMEM  ((AR_OFF + MPAD)*4)             // 100032 B

__global__ __launch_bounds__(320, 2) void attn_tc(const float* __restrict__ mask) {
    extern __shared__ float sm[];
    float* Qs = sm + AQ_OFF;       // [80][36]  (rows 72..79 zero)
    float* Ks = sm + AK_OFF;       // [144][36]
    float* Vs = sm + AV_OFF;       // [144][36]
    float* Ss = sm + AS_OFF;       // [80][146]
    float* rinv = sm + AR_OFF;     // [80]
    float* P2 = Qs;                // PV partials reuse Q tile [80][36]

    int tid = threadIdx.x;
    int bid = blockIdx.x;
    int wh = bid / (2 * B_TOT);          // bias L2 reuse across 30 CTAs
    int r2 = bid - wh * (2 * B_TOT);
    int b_ = r2 >> 1;
    int hb = r2 & 1;                     // which 72-row half
    int w_ = wh / NH;
    int h  = wh - w_ * NH;

    const float* qp = g_q + ((size_t)b_ * WHCNT + wh) * (NSEQ * LDIM) + hb * HROWS * LDIM;
    const float* kp = g_k + ((size_t)b_ * WHCNT + wh) * (NSEQ * LDIM);
    const float* vp = g_v + ((size_t)b_ * WHCNT + wh) * (NSEQ * LDIM);

    // ---- zero pad rows of Q tile ----
    if (tid < 72) {
        *(float4*)(Qs + HROWS * ASTR + tid * 4) = make_float4(0.f, 0.f, 0.f, 0.f);
    }
    // ---- async load Q(72x32), K(144x32), V(144x32), raw fp32 bits ----
    {
        uint32_t sb = (uint32_t)__cvta_generic_to_shared(sm);
#pragma unroll
        for (int v = tid; v < HROWS * 8; v += 320) {
            int n = v >> 3, c4 = (v & 7) << 2;
            cp16(sb + ((AQ_OFF + n * ASTR + c4) << 2), qp + n * LDIM + c4);
        }
#pragma unroll
        for (int v = tid; v < NSEQ * 8; v += 320) {
            int n = v >> 3, c4 = (v & 7) << 2;
            cp16(sb + ((AK_OFF + n * ASTR + c4) << 2), kp + n * LDIM + c4);
            cp16(sb + ((AV_OFF + n * ASTR + c4) << 2), vp + n * LDIM + c4);
        }
        cp_commit();
        cp_wait<0>();
    }
    __syncthreads();

    int wid = tid >> 5, t = tid & 31;
    int tq = t & 3, tr = t >> 2;

    // ---- mma1: S = Q @ K^T (80x144x32), warp grid 5m x 2nh ----
    {
        int wm = wid >> 1, nh = wid & 1;
        float c[9][4];
#pragma unroll
        for (int ni = 0; ni < 9; ni++)
#pragma unroll
            for (int f = 0; f < 4; f++) c[ni][f] = 0.f;

        const uint32_t* Qu = (const uint32_t*)Qs;
        const uint32_t* Ku = (const uint32_t*)Ks;
#pragma unroll
        for (int ks = 0; ks < 4; ks++) {
            int k0 = ks * 8;
            uint32_t a[4];
            const uint32_t* ap = Qu + (wm * 16 + tr) * ASTR + k0 + tq;
            a[0] = ap[0]; a[1] = ap[8 * ASTR]; a[2] = ap[4]; a[3] = ap[8 * ASTR + 4];
#pragma unroll
            for (int ni = 0; ni < 9; ni++) {
                uint32_t b[2];
                const uint32_t* bp2 = Ku + (nh * 72 + ni * 8 + tr) * ASTR + k0 + tq;
                b[0] = bp2[0]; b[1] = bp2[4];
                mma8(c[ni], a, b);
            }
        }

        const float scale = 0.17677669529663687f;   // 32^-0.5
        int n0l = wm * 16 + tr, n1l = n0l + 8;      // n0l always < 72
        int gn0 = hb * HROWS + n0l, gn1 = gn0 + 8;
        const float* bp = g_bias + (size_t)wh * NN;
        const float* mp = mask + ((size_t)b_ * NW + w_) * NN;
        bool ok1 = (n1l < HROWS);
#pragma unroll
        for (int ni = 0; ni < 9; ni++) {
            int m0 = nh * 72 + ni * 8 + 2 * tq;
            float2 bb0 = *(const float2*)(bp + (size_t)gn0 * NSEQ + m0);
            float2 mm0 = *(const float2*)(mp + (size_t)gn0 * NSEQ + m0);
            *(float2*)(Ss + n0l * SSTR + m0) =
                make_float2(c[ni][0] * scale + bb0.x + mm0.x,
                            c[ni][1] * scale + bb0.y + mm0.y);
            if (ok1) {
                float2 bb1 = *(const float2*)(bp + (size_t)gn1 * NSEQ + m0);
                float2 mm1 = *(const float2*)(mp + (size_t)gn1 * NSEQ + m0);
                *(float2*)(Ss + n1l * SSTR + m0) =
                    make_float2(c[ni][2] * scale + bb1.x + mm1.x,
                                c[ni][3] * scale + bb1.y + mm1.y);
            } else {
                *(float2*)(Ss + n1l * SSTR + m0) = make_float2(0.f, 0.f);
            }
        }
    }
    __syncthreads();

    // ---- softmax: 4 threads per row (72 rows -> 288 threads) ----
    if (tid < 288) {
        int n = tid >> 2, seg = tid & 3;
        float* row = Ss + n * SSTR + seg * 36;
        float mx = -1e30f;
#pragma unroll
        for (int i = 0; i < 36; i++) mx = fmaxf(mx, row[i]);
        mx = fmaxf(mx, __shfl_xor_sync(0xffffffffu, mx, 1));
        mx = fmaxf(mx, __shfl_xor_sync(0xffffffffu, mx, 2));
        float s = 0.f;
#pragma unroll
        for (int i = 0; i < 36; i++) {
            float e = __expf(row[i] - mx);
            s += e;
            row[i] = e;                   // raw fp32; mma truncates to tf32
        }
        s += __shfl_xor_sync(0xffffffffu, s, 1);
        s += __shfl_xor_sync(0xffffffffu, s, 2);
        if (seg == 0) rinv[n] = 1.0f / s;
    }
    __syncthreads();

    // ---- PV: out = P @ V (80x32x144), warp grid 5m x 2kh (split-K) ----
    {
        int wm = wid % 5, kh = wid / 5;
        float c2[4][4];
#pragma unroll
        for (int ni = 0; ni < 4; ni++)
#pragma unroll
            for (int f = 0; f < 4; f++) c2[ni][f] = 0.f;

        const uint32_t* Su = (const uint32_t*)Ss;
        const uint32_t* Vu = (const uint32_t*)Vs;
#pragma unroll
        for (int ks = 0; ks < 9; ks++) {
            int k0 = kh * 72 + ks * 8;
            uint32_t a[4];
            const uint32_t* ap = Su + (wm * 16 + tr) * SSTR + k0 + tq;
            a[0] = ap[0]; a[1] = ap[8 * SSTR]; a[2] = ap[4]; a[3] = ap[8 * SSTR + 4];
#pragma unroll
            for (int ni = 0; ni < 4; ni++) {
                uint32_t b[2];
                const uint32_t* bp2 = Vu + (k0 + tq) * ASTR + ni * 8 + tr;
                b[0] = bp2[0]; b[1] = bp2[4 * ASTR];
                mma8(c2[ni], a, b);
            }
        }

        if (kh == 1) {
            int n0 = wm * 16 + tr;
#pragma unroll
            for (int ni = 0; ni < 4; ni++) {
                int l0 = ni * 8 + 2 * tq;
                *(float2*)(P2 + n0 * ASTR + l0) = make_float2(c2[ni][0], c2[ni][1]);
                *(float2*)(P2 + (n0 + 8) * ASTR + l0) = make_float2(c2[ni][2], c2[ni][3]);
            }
        }
        __syncthreads();
        if (kh == 0) {
            int n0l = wm * 16 + tr, n1l = n0l + 8;   // n0l always < 72
            int gn0 = hb * HROWS + n0l;
            float* yp = g_y + (((size_t)b_ * NW + w_) * NSEQ) * CDIM + h * LDIM;
            float r0 = rinv[n0l];
            bool ok1 = (n1l < HROWS);
            float r1 = ok1 ? rinv[n1l] : 0.f;
#pragma unroll
            for (int ni = 0; ni < 4; ni++) {
                int l0 = ni * 8 + 2 * tq;
                float2 p0 = *(float2*)(P2 + n0l * ASTR + l0);
                *(float2*)(yp + (size_t)gn0 * CDIM + l0) =
                    make_float2((c2[ni][0] + p0.x) * r0, (c2[ni][1] + p0.y) * r0);
                if (ok1) {
                    float2 p1 = *(float2*)(P2 + n1l * ASTR + l0);
                    *(float2*)(yp + (size_t)(gn0 + 8) * CDIM + l0) =
                        make_float2((c2[ni][2] + p1.x) * r1, (c2[ni][3] + p1.y) * r1);
                }
            }
        }
    }
}

// ---------------- launch ----------------
extern "C" void kernel_launch(void* const* d_in, const int* in_sizes, int n_in,
                              void* d_out, int out_size) {
    const float* x          = (const float*)d_in[0];
    const float* mask       = (const float*)d_in[1];
    const float* qkv_w      = (const float*)d_in[2];
    const float* qkv_b      = (const float*)d_in[3];
    const float* proj_w     = (const float*)d_in[4];
    const float* proj_b     = (const float*)d_in[5];
    const float* bias_table = (const float*)d_in[6];
    float* out = (float*)d_out;

    cudaFuncSetAttribute(qkv_gemm_tc, cudaFuncAttributeMaxDynamicSharedMemorySize, GSMEM);
    cudaFuncSetAttribute(proj_gemm_tc, cudaFuncAttributeMaxDynamicSharedMemorySize, GSMEM);
    cudaFuncSetAttribute(attn_tc, cudaFuncAttributeMaxDynamicSharedMemorySize, ASMEM);

    bias_gather_kernel<<<WHCNT, 256>>>(bias_table);
    qkv_gemm_tc<<<dim3(MROWS / GBM, QKV_N / GBN), 256, GSMEM>>>(x, qkv_w, qkv_b);
    attn_tc<<<2 * B_TOT * WHCNT, 320, ASMEM>>>(mask);
    proj_gemm_tc<<<dim3(MROWS / GBM, CDIM / GBN), 256, GSMEM>>>(proj_w, proj_b, out);
}